// round 14
// baseline (speedup 1.0000x reference)
#include <cuda_runtime.h>

// 2-layer LSTM (B=256, T=512, I=64, H=256) + FC(H->1), fp32.
// Persistent kernel, 128 CTAs x 256 threads, CTA tile 32 batch x 16 units.
// Weights resident in smem. 4b x 4c FFMA2 tile, depth-2 pipelined.
// K split across two warp-sets (2 warps/SMSP) + packed-f32x2 reduction.
// x-part GEMM before the group wait; one-way flag group sync.

#define BB   256
#define TT   512
#define II   64
#define HH   256

#define GRID 128
#define NTHR 256
#define GSIZE 16

typedef unsigned long long ull;

// ---------------- device globals (scratch) ---------------------------------
__device__ float g_hbuf[2][BB * HH];
__device__ float g_h1[(size_t)BB * TT * HH];
__device__ int          g_flag[8 * 32];
__device__ ull          g_gen8[8 * 32];
__device__ unsigned int g_cnt8[8 * 32];

// ---------------- startup atomic barrier (replay-safe) ----------------------
__device__ __forceinline__ void group_barrier_atomic(int g) {
    __syncthreads();
    __threadfence();
    if (threadIdx.x == 0) {
        volatile ull* genp = &g_gen8[g * 32];
        ull my = *genp;
        unsigned prev = atomicAdd(&g_cnt8[g * 32], 1u);
        if (prev == GSIZE - 1u) {
            g_cnt8[g * 32] = 0u;
            __threadfence();
            atomicAdd((ull*)&g_gen8[g * 32], 1ULL);
        } else {
            while (*genp == my) __nanosleep(32);
        }
        __threadfence();
    }
    __syncthreads();
}

// ---------------- flag sync -------------------------------------------------
__device__ __forceinline__ void wait_group(int grp, int target) {
    if (threadIdx.x < GSIZE) {
        volatile int* f = &g_flag[grp * 32 + threadIdx.x];
        while (*f < target) { }
    }
    __syncthreads();
}
__device__ __forceinline__ void publish(int grp, int j, int epoch) {
    __syncthreads();
    if (threadIdx.x == 0) {
        __threadfence();
        *(volatile int*)&g_flag[grp * 32 + j] = epoch;
    }
}

// ---------------- packed f32x2 helpers -------------------------------------
__device__ __forceinline__ void fma2(ull& d, ull a, ull b) {
    asm("fma.rn.f32x2 %0, %1, %2, %0;" : "+l"(d) : "l"(a), "l"(b));
}
__device__ __forceinline__ ull add2(ull a, ull b) {
    ull r;
    asm("add.rn.f32x2 %0, %1, %2;" : "=l"(r) : "l"(a), "l"(b));
    return r;
}
__device__ __forceinline__ ull pack2(float lo, float hi) {
    ull v;
    asm("mov.b64 %0, {%1, %2};" : "=l"(v) : "f"(lo), "f"(hi));
    return v;
}
__device__ __forceinline__ float2 unpack2(ull v) {
    float2 f;
    asm("mov.b64 {%0, %1}, %2;" : "=f"(f.x), "=f"(f.y) : "l"(v));
    return f;
}

// ---------------- activations ----------------------------------------------
__device__ __forceinline__ float fsigmoid(float x) {
    return 1.0f / (1.0f + __expf(-x));
}
__device__ __forceinline__ float ftanh(float x) {
    x = fminf(15.0f, fmaxf(-15.0f, x));
    float t = __expf(2.0f * x);
    return (t - 1.0f) / (t + 1.0f);
}

// Dynamic smem (floats), K = HH + KIN:
//   ws   [K][68]       weight slice, k-major (272B rows)
//   as   [K][36]+pad   A tile ([h | x]); x-rows region doubles as 'red'
//   sg   [32][68]      gate pre-activations
//   cs   [512], bias [64]
extern __shared__ float smbuf[];

// ---------------- A staging: chunks of 32 k-rows (256 threads) --------------
template<int KIN>
__device__ __forceinline__ void stage_A(float* as, int c0, int c1, int t, int mbase,
                                        const float* __restrict__ hr,
                                        const float* __restrict__ xin) {
    const int bb  = threadIdx.x >> 3;          // 0..31
    const int kof = (threadIdx.x & 7) * 4;
    for (int c = c0; c < c1; c++) {
        int k = c * 32 + kof;
        const float* src;
        if (k < HH) src = hr + (mbase + bb) * HH + k;
        else {
            if (KIN == HH)
                src = xin + ((size_t)(mbase + bb) * TT + t) * HH + (k - HH);
            else
                src = xin + ((size_t)(mbase + bb) * TT + t) * II + (k - HH);
        }
        float4 a = __ldcg((const float4*)src);
        as[(k + 0) * 36 + bb] = a.x;
        as[(k + 1) * 36 + bb] = a.y;
        as[(k + 2) * 36 + bb] = a.z;
        as[(k + 3) * 36 + bb] = a.w;
    }
}

// ---------------- GEMM over k-range [k0, k1), depth-2 pipelined -------------
#define GMATH(AV, W) do {                                                     \
    ull wxx = pack2((W).x, (W).x), wyy = pack2((W).y, (W).y);                 \
    ull wzz = pack2((W).z, (W).z), www = pack2((W).w, (W).w);                 \
    fma2(acc[0][0], (AV).x, wxx); fma2(acc[0][1], (AV).x, wyy);               \
    fma2(acc[0][2], (AV).x, wzz); fma2(acc[0][3], (AV).x, www);               \
    fma2(acc[1][0], (AV).y, wxx); fma2(acc[1][1], (AV).y, wyy);               \
    fma2(acc[1][2], (AV).y, wzz); fma2(acc[1][3], (AV).y, www);               \
} while (0)

__device__ __forceinline__ void gemm_range(ull (&acc)[2][4],
                                           const float* __restrict__ as,
                                           const float* __restrict__ ws,
                                           int k0, int k1, int b4, int c4) {
    const float* ap = as + k0 * 36 + b4;
    const float* wp = ws + k0 * 68 + c4;
    const int n = k1 - k0;
    ulonglong2 av0 = *(const ulonglong2*)ap;
    float4     w0  = *(const float4*)wp;
    ulonglong2 av1 = *(const ulonglong2*)(ap + 36);
    float4     w1  = *(const float4*)(wp + 68);
    ap += 72; wp += 136;
#pragma unroll 8
    for (int kk = 0; kk < n - 2; kk++) {
        ulonglong2 av2 = *(const ulonglong2*)ap;
        float4     w2  = *(const float4*)wp;
        ap += 36; wp += 68;
        GMATH(av0, w0);
        av0 = av1; w0 = w1;
        av1 = av2; w1 = w2;
    }
    GMATH(av0, w0);
    GMATH(av1, w1);
}

// ---------------- one LSTM layer -------------------------------------------
template<int KIN, bool ARCHIVE>
__device__ void run_layer(int base, const float* __restrict__ xin,
                          const float* __restrict__ Wih,
                          const float* __restrict__ Whh,
                          const float* __restrict__ bih,
                          const float* __restrict__ bhh) {
    constexpr int K = HH + KIN;
    float* ws   = smbuf;                       // [K][68]
    float* as   = smbuf + K * 68;              // [K][36] (+pad)
    float* sg   = as + K * 36 + 320;           // [32][68]
    float* cs   = sg + 32 * 68;                // [512]
    float* bias = cs + 512;                    // [64]
    ull*   red  = (ull*)(as + HH * 36);        // overlays x-rows: 128*10 ull

    const int tid   = threadIdx.x;
    const int grp   = blockIdx.x >> 4;
    const int jj    = blockIdx.x & 15;
    const int mbase = grp * 32;
    const int jbase = jj * 16;

    wait_group(grp, base);                     // layer entry gate

    // ---- init: weight slice -> smem, zero c / h(-1), biases ----
    constexpr int K4 = K / 4;
    for (int idx = tid; idx < 64 * K4; idx += NTHR) {
        int cc = idx / K4;
        int k  = (idx - cc * K4) * 4;
        int gate = cc >> 4, u = cc & 15;
        int grow = gate * HH + jbase + u;
        const float* src = (k < HH) ? (Whh + grow * HH + k)
                                    : (Wih + grow * KIN + k - HH);
        float4 w = *(const float4*)src;
        ws[(k + 0) * 68 + cc] = w.x;
        ws[(k + 1) * 68 + cc] = w.y;
        ws[(k + 2) * 68 + cc] = w.z;
        ws[(k + 3) * 68 + cc] = w.w;
    }
    for (int idx = tid; idx < 512; idx += NTHR) {
        cs[idx] = 0.0f;
        int bb = idx >> 4, u = idx & 15;
        __stcg(&g_hbuf[0][(mbase + bb) * HH + jbase + u], 0.0f);
    }
    if (tid < 64) {
        int gate = tid >> 4, u = tid & 15;
        int grow = gate * HH + jbase + u;
        bias[tid] = bih[grow] + bhh[grow];
    }
    publish(grp, jj, base + 1);

    // prologue: stage x-part for t=0
    stage_A<KIN>(as, HH / 32, K / 32, 0, mbase, nullptr, xin);
    __syncthreads();

    const int sset = tid >> 7;                 // warp-set 0/1
    const int stid = tid & 127;
    const int b4 = (stid & 7) * 4;
    const int c4 = (stid >> 3) * 4;
    constexpr int XH = KIN / 2;
    const int x0 = HH + sset * XH, x1 = x0 + XH;
    const int h0 = sset * (HH / 2), h1e = h0 + HH / 2;

    for (int t = 0; t < TT; t++) {
        const float* hr = g_hbuf[t & 1];
        float*       hw = g_hbuf[(t & 1) ^ 1];

        ull acc[2][4];
#pragma unroll
        for (int p = 0; p < 2; p++)
#pragma unroll
            for (int c = 0; c < 4; c++) acc[p][c] = 0ULL;

        // x-part (independent of h(t-1)) — absorbs group skew
        gemm_range(acc, as, ws, x0, x1, b4, c4);

        // wait for h(t-1), stage it (all 256 threads), finish this set's half
        wait_group(grp, base + 1 + t);
        stage_A<KIN>(as, 0, HH / 32, t, mbase, hr, xin);
        __syncthreads();
        gemm_range(acc, as, ws, h0, h1e, b4, c4);

        // ---- cross-set reduction (red overlays x-rows; races excluded by
        //      the wait_group sync before this point and the syncs below) ----
        if (sset == 1) {
#pragma unroll
            for (int p = 0; p < 2; p++)
#pragma unroll
                for (int c = 0; c < 4; c++)
                    red[stid * 10 + p * 4 + c] = acc[p][c];
        }
        __syncthreads();
        if (sset == 0) {
#pragma unroll
            for (int p = 0; p < 2; p++)
#pragma unroll
                for (int c = 0; c < 4; c++)
                    acc[p][c] = add2(acc[p][c], red[stid * 10 + p * 4 + c]);
            // stage gate pre-activations
#pragma unroll
            for (int p = 0; p < 2; p++) {
                float2 f0 = unpack2(acc[p][0]);
                float2 f1 = unpack2(acc[p][1]);
                float2 f2 = unpack2(acc[p][2]);
                float2 f3 = unpack2(acc[p][3]);
                *(float4*)&sg[(b4 + 2 * p + 0) * 68 + c4] =
                    make_float4(f0.x, f1.x, f2.x, f3.x);
                *(float4*)&sg[(b4 + 2 * p + 1) * 68 + c4] =
                    make_float4(f0.y, f1.y, f2.y, f3.y);
            }
        }
        __syncthreads();

        // ---- LSTM pointwise: 512 (b,u) pairs / 256 threads ----
#pragma unroll
        for (int r = 0; r < 2; r++) {
            int pair = tid * 2 + r;
            int bb = pair >> 4;
            int u  = pair & 15;
            float pi = sg[bb * 68 + u]      + bias[u];
            float pf = sg[bb * 68 + 16 + u] + bias[16 + u];
            float pg = sg[bb * 68 + 32 + u] + bias[32 + u];
            float po = sg[bb * 68 + 48 + u] + bias[48 + u];
            float ig = fsigmoid(pi);
            float fg = fsigmoid(pf);
            float gg = ftanh(pg);
            float og = fsigmoid(po);
            float cv = fg * cs[bb * 16 + u] + ig * gg;
            cs[bb * 16 + u] = cv;
            float hv = og * ftanh(cv);
            __stcg(&hw[(mbase + bb) * HH + jbase + u], hv);
            if (ARCHIVE)
                __stcg(&g_h1[(size_t)((mbase + bb) * TT + t) * HH + jbase + u], hv);
        }

        // prefetch x-part for t+1 (after red reads: protected by sync above)
        if (t + 1 < TT)
            stage_A<KIN>(as, HH / 32, K / 32, t + 1, mbase, nullptr, xin);

        publish(grp, jj, base + 2 + t);
    }
}

// ---------------- full model -----------------------------------------------
__global__ void __launch_bounds__(NTHR, 1)
lstm_persistent_kernel(const float* __restrict__ x,
                       const float* __restrict__ Wih0, const float* __restrict__ Whh0,
                       const float* __restrict__ bih0, const float* __restrict__ bhh0,
                       const float* __restrict__ Wih1, const float* __restrict__ Whh1,
                       const float* __restrict__ bih1, const float* __restrict__ bhh1,
                       const float* __restrict__ Wfc,  const float* __restrict__ bfc,
                       float* __restrict__ out) {
    const int grp = blockIdx.x >> 4;
    const int jj  = blockIdx.x & 15;

    if (threadIdx.x == 0)
        *(volatile int*)&g_flag[grp * 32 + jj] = 0;
    group_barrier_atomic(grp);

    run_layer<II, true >(0,      x,    Wih0, Whh0, bih0, bhh0);  // epochs 1..513
    run_layer<HH, false>(TT + 1, g_h1, Wih1, Whh1, bih1, bhh1);  // 514..1026

    if (jj == 0) {
        wait_group(grp, 2 * TT + 2);
        int mbase = grp * 32;
        for (int bb = threadIdx.x; bb < 32; bb += NTHR) {
            float s = bfc[0];
#pragma unroll 8
            for (int j = 0; j < HH; j++)
                s += __ldcg(&g_hbuf[0][(mbase + bb) * HH + j]) * Wfc[j];
            out[mbase + bb] = s;
        }
    }
}

// ---------------- harness entry --------------------------------------------
extern "C" void kernel_launch(void* const* d_in, const int* in_sizes, int n_in,
                              void* d_out, int out_size) {
    (void)in_sizes; (void)n_in; (void)out_size;
    const float* x    = (const float*)d_in[0];
    const float* Wih0 = (const float*)d_in[1];
    const float* Whh0 = (const float*)d_in[2];
    const float* bih0 = (const float*)d_in[3];
    const float* bhh0 = (const float*)d_in[4];
    const float* Wih1 = (const float*)d_in[5];
    const float* Whh1 = (const float*)d_in[6];
    const float* bih1 = (const float*)d_in[7];
    const float* bhh1 = (const float*)d_in[8];
    const float* Wfc  = (const float*)d_in[9];
    const float* bfc  = (const float*)d_in[10];

    // L1 footprint: 512*68 + 512*36 + 320 + 32*68 + 512 + 64 = 56320 floats
    const int smem_bytes = 56320 * 4;          // 225,280 B
    cudaFuncSetAttribute(lstm_persistent_kernel,
                         cudaFuncAttributeMaxDynamicSharedMemorySize, smem_bytes);

    lstm_persistent_kernel<<<GRID, NTHR, smem_bytes>>>(
        x, Wih0, Whh0, bih0, bhh0,
        Wih1, Whh1, bih1, bhh1,
        Wfc, bfc, (float*)d_out);
}